// round 12
// baseline (speedup 1.0000x reference)
#include <cuda_runtime.h>
#include <cuda_fp16.h>

// ---------------------------------------------------------------------------
// SSIM fusion loss: 1 - (SSIM(f,s1)+SSIM(f,s2))/2, single fused kernel.
// 5 CTAs/SM: phased smem aliasing + fp16 hint. hpass: packed f32x2 FFMA2 in
// two field-group loops (register-lean). vpass: LDS.32 half2 + HFMA2,
// warp-specialized row base. Deterministic Q32 fixed-point reduction.
// ---------------------------------------------------------------------------

#define IMH 512
#define IMW 512
#define TW 32
#define TH 32
#define EXT 42
#define RSTR 44                  // raw per-plane row stride (floats)
#define RS3 132                  // raw row stride = 3*RSTR (floats)
#define HROW2 144                // hint row stride in half2 units (4 pairs * 36)
#define PST2 36                  // half2 units per pair within a row
#define R1 30                    // phase-A hint rows (0..29)
#define RAW_FLOATS 5544          // 42*132
#define NTHREADS 256
#define GX 16
#define GY 16
#define NPLANES 48
#define NBLOCKS (GX*GY*NPLANES)
#define NTOT 12582912.0
#define FPSCALE 4294967296.0
#define SMEM_BYTES (RAW_FLOATS*4 + R1*HROW2*4)   // 22176 + 17280 = 39456 B

typedef unsigned long long u64;

__device__ u64      g_accs[NPLANES];
__device__ unsigned g_count = 0u;

// Gaussian weights (sigma=1.5, 11 taps, normalized) as pure literals.
#define W0f 0.00102838f
#define W1f 0.00759876f
#define W2f 0.03600077f
#define W3f 0.10936069f
#define W4f 0.21300554f
#define W5f 0.26601173f
#define WW(j) ( (j)==5 ? W5f : ((j)==4||(j)==6) ? W4f : ((j)==3||(j)==7) ? W3f \
              : ((j)==2||(j)==8) ? W2f : ((j)==1||(j)==9) ? W1f : W0f )

// ---- packed f32x2 helpers -------------------------------------------------
__device__ __forceinline__ u64 pack2(float lo, float hi) {
    u64 r;
    asm("mov.b64 %0, {%1, %2};" : "=l"(r)
        : "r"(__float_as_uint(lo)), "r"(__float_as_uint(hi)));
    return r;
}
__device__ __forceinline__ void unpack2(u64 v, float& lo, float& hi) {
    unsigned a, b;
    asm("mov.b64 {%0, %1}, %2;" : "=r"(a), "=r"(b) : "l"(v));
    lo = __uint_as_float(a); hi = __uint_as_float(b);
}
__device__ __forceinline__ u64 fma2(u64 a, u64 b, u64 c) {
    u64 d;
    asm("fma.rn.f32x2 %0, %1, %2, %3;" : "=l"(d) : "l"(a), "l"(b), "l"(c));
    return d;
}
__device__ __forceinline__ u64 mul2(u64 a, u64 b) {
    u64 d;
    asm("mul.rn.f32x2 %0, %1, %2;" : "=l"(d) : "l"(a), "l"(b));
    return d;
}
__device__ __forceinline__ __half2 u64_to_h2(u64 v) {
    float lo, hi;
    unpack2(v, lo, hi);
    return __floats2half2_rn(lo, hi);
}

// One packed hpass field-group loop. PAIRSEL 0: pairs (f,a),(b,f^2).
// PAIRSEL 1: pairs (a^2,b^2),(f*a,f*b). Streams the raw row per-q; per-field
// fp32 accumulation order (cc ascending) identical to the scalar version.
#define HPASS_PACKED(RAWBASE, H2BASE, PAIRSEL)                                \
{                                                                             \
    u64 pacc[2][4];                                                           \
    _Pragma("unroll")                                                         \
    for (int pp = 0; pp < 2; ++pp)                                            \
        _Pragma("unroll")                                                     \
        for (int o = 0; o < 4; ++o) pacc[pp][o] = 0ULL;                       \
    _Pragma("unroll")                                                         \
    for (int q = 0; q < 4; ++q) {                                             \
        float4 Lf = *reinterpret_cast<const float4*>(&smem[(RAWBASE) + 0*RSTR + c0 + 4*q]); \
        float4 La = *reinterpret_cast<const float4*>(&smem[(RAWBASE) + 1*RSTR + c0 + 4*q]); \
        float4 Lb = *reinterpret_cast<const float4*>(&smem[(RAWBASE) + 2*RSTR + c0 + 4*q]); \
        float qf[4] = {Lf.x, Lf.y, Lf.z, Lf.w};                               \
        float qa[4] = {La.x, La.y, La.z, La.w};                               \
        float qb[4] = {Lb.x, Lb.y, Lb.z, Lb.w};                               \
        _Pragma("unroll")                                                     \
        for (int t = 0; t < 4; ++t) {                                         \
            const int cc = 4*q + t;                                           \
            if (cc < 14) {                                                    \
                float f = qf[t], a = qa[t], b = qb[t];                        \
                u64 x0, x1;                                                   \
                if (PAIRSEL == 0) {                                           \
                    x0 = pack2(f, a);                                         \
                    x1 = pack2(b, f * f);                                     \
                } else {                                                      \
                    u64 pab = pack2(a, b);                                    \
                    x0 = mul2(pab, pab);                                      \
                    x1 = mul2(pack2(f, f), pab);                              \
                }                                                             \
                _Pragma("unroll")                                             \
                for (int o = 0; o < 4; ++o) {                                 \
                    const int j = cc - o;                                     \
                    if (j >= 0 && j < 11) {                                   \
                        const u64 w = wq[(j < 6) ? j : (10 - j)];             \
                        pacc[0][o] = fma2(w, x0, pacc[0][o]);                 \
                        pacc[1][o] = fma2(w, x1, pacc[1][o]);                 \
                    }                                                         \
                }                                                             \
            }                                                                 \
        }                                                                     \
    }                                                                         \
    _Pragma("unroll")                                                         \
    for (int pp = 0; pp < 2; ++pp) {                                          \
        const int p = (PAIRSEL)*2 + pp;                                       \
        __half2 h0 = u64_to_h2(pacc[pp][0]);                                  \
        __half2 h1 = u64_to_h2(pacc[pp][1]);                                  \
        __half2 h2 = u64_to_h2(pacc[pp][2]);                                  \
        __half2 h3 = u64_to_h2(pacc[pp][3]);                                  \
        uint4 st;                                                             \
        st.x = *reinterpret_cast<unsigned*>(&h0);                             \
        st.y = *reinterpret_cast<unsigned*>(&h1);                             \
        st.z = *reinterpret_cast<unsigned*>(&h2);                             \
        st.w = *reinterpret_cast<unsigned*>(&h3);                             \
        *reinterpret_cast<uint4*>(&hintS[(H2BASE) + p*PST2 + c0]) = st;       \
    }                                                                         \
}

// vpass accumulation over 14 hint rows starting at r0v.
#define VPASS_LOOP(ROWPTR)                                                    \
    _Pragma("unroll")                                                         \
    for (int jj = 0; jj < 14; ++jj) {                                         \
        const int row = r0v + jj;                                             \
        const __half2* rowp = ROWPTR(row);                                    \
        __half2 v[4];                                                         \
        _Pragma("unroll")                                                     \
        for (int p = 0; p < 4; ++p)                                           \
            v[p] = rowp[p * PST2 + col];                                      \
        _Pragma("unroll")                                                     \
        for (int o = 0; o < 4; ++o) {                                         \
            const int j = jj - o;                                             \
            if (j >= 0 && j < 11) {                                           \
                const __half2 w = wh[(j < 6) ? j : (10 - j)];                 \
                _Pragma("unroll")                                             \
                for (int p = 0; p < 4; ++p)                                   \
                    acc[p][o] = __hfma2(w, v[p], acc[p][o]);                  \
            }                                                                 \
        }                                                                     \
    }

__global__ __launch_bounds__(NTHREADS, 5)
void ssim_fused_kernel(const float* __restrict__ F,
                       const float* __restrict__ S1,
                       const float* __restrict__ S2,
                       float* __restrict__ out)
{
    extern __shared__ float smem[];
    // [0 .. 22176)B      raw[42][3][44] fp32 (rows <=13 later overlaid)
    // [22176 .. 39456)B  hintA rows 0..29: [30][4 pairs][36] half2
    // [0 .. 6912)B       hintB rows 30..41: [12][4 pairs][36] half2
    __half2* hint2B = reinterpret_cast<__half2*>(smem);
    __half2* hint2A = reinterpret_cast<__half2*>(smem + RAW_FLOATS);

    const int tid  = threadIdx.x;
    const int wid  = tid >> 5;
    const int lane = tid & 31;

    const int bx = blockIdx.x, by = blockIdx.y, bz = blockIdx.z;
    const int plane = bz * (IMH * IMW);
    const int y0 = by * TH - 5;

    // ---- Vectorized halo load ---------------------------------------------
    for (int i = tid; i < EXT * 3 * 12; i += NTHREADS) {
        const int q  = i % 12;
        const int rp = i / 12;
        const int r  = rp / 3;
        const int p  = rp - r * 3;
        const int gy = y0 + r;
        const int gx0 = bx * TW - 8 + q * 4;
        const bool ok = (gy >= 0) && (gy < IMH) && (gx0 >= 0) && (gx0 <= IMW - 4);

        const float* src = (p == 0) ? F : (p == 1) ? S1 : S2;
        float4 v = make_float4(0.f, 0.f, 0.f, 0.f);
        if (ok)
            v = *reinterpret_cast<const float4*>(src + plane + gy * IMW + gx0);

        const int cb = q * 4 - 3;
        float* dst = &smem[r * RS3 + p * RSTR];
        if (cb + 0 >= 0 && cb + 0 < EXT) dst[cb + 0] = v.x;
        if (cb + 1 >= 0 && cb + 1 < EXT) dst[cb + 1] = v.y;
        if (cb + 2 >= 0 && cb + 2 < EXT) dst[cb + 2] = v.z;
        if (cb + 3 < EXT)                dst[cb + 3] = v.w;
    }
    __syncthreads();

    // packed (w,w) weights for the f32x2 hpass (6 unique)
    u64 wq[6];
    #pragma unroll
    for (int j = 0; j < 6; ++j) wq[j] = pack2(WW(j), WW(j));

    // ---- Horizontal pass, phase A: rows 0..29 -> hintA --------------------
    if (tid < R1 * 8) {
        const int r  = tid >> 3;
        const int c0 = (tid & 7) * 4;
        __half2* hintS = hint2A;
        HPASS_PACKED(r * RS3, r * HROW2, 0)
        HPASS_PACKED(r * RS3, r * HROW2, 1)
    }
    __syncthreads();

    // ---- Phase B: rows 30..41 -> hintB at smem[0] (overlays raw rows <=13)
    if (tid < 12 * 8) {
        const int rr = tid >> 3;            // 0..11 -> row 30+rr
        const int c0 = (tid & 7) * 4;
        __half2* hintS = hint2B;
        HPASS_PACKED((R1 + rr) * RS3, rr * HROW2, 0)
        HPASS_PACKED((R1 + rr) * RS3, rr * HROW2, 1)
    }
    __syncthreads();

    // ---- Vertical pass (half2/HFMA2) + SSIM: thread = 1 col x 4 rows ------
    const int col = lane;
    const int r0v = wid * 4;

    __half2 wh[6];
    #pragma unroll
    for (int j = 0; j < 6; ++j) wh[j] = __floats2half2_rn(WW(j), WW(j));

    __half2 acc[4][4];  // [pair][out]
    #pragma unroll
    for (int p = 0; p < 4; ++p)
        #pragma unroll
        for (int o = 0; o < 4; ++o) acc[p][o] = __floats2half2_rn(0.f, 0.f);

    #define ROWPTR_A(row)   (&hint2A[(row) * HROW2])
    #define ROWPTR_MIX(row) ((row) < R1 ? &hint2A[(row) * HROW2]              \
                                        : &hint2B[((row) - R1) * HROW2])
    if (r0v + 13 < R1) {        // warps 0..4: rows entirely in hintA
        VPASS_LOOP(ROWPTR_A)
    } else {                    // warps 5..7: mixed A/B rows
        VPASS_LOOP(ROWPTR_MIX)
    }

    const float C1 = 1e-4f;
    const float C2 = 9e-4f;
    float lsum = 0.f;
    #pragma unroll
    for (int o = 0; o < 4; ++o) {
        float muF = __low2float (acc[0][o]);
        float mu1 = __high2float(acc[0][o]);
        float mu2 = __low2float (acc[1][o]);
        float eFF = __high2float(acc[1][o]);
        float e11 = __low2float (acc[2][o]);
        float e22 = __high2float(acc[2][o]);
        float eF1 = __low2float (acc[3][o]);
        float eF2 = __high2float(acc[3][o]);

        float mFF = muF*muF, m11 = mu1*mu1, m22 = mu2*mu2;
        float pF1 = muF*mu1, pF2 = muF*mu2;

        float sF  = eFF - mFF;
        float s11 = e11 - m11;
        float s22 = e22 - m22;
        float c1v = eF1 - pF1;
        float c2v = eF2 - pF2;

        float num1 = (2.f*pF1 + C1) * (2.f*c1v + C2);
        float den1 = (mFF + m11 + C1) * (sF + s11 + C2);
        float num2 = (2.f*pF2 + C1) * (2.f*c2v + C2);
        float den2 = (mFF + m22 + C1) * (sF + s22 + C2);

        lsum += __fdividef(num1*den2 + num2*den1, den1*den2);
    }

    // ---- Reduction: warp shuffle -> block -> Q32 atomic (48 slots) --------
    #pragma unroll
    for (int off = 16; off > 0; off >>= 1)
        lsum += __shfl_xor_sync(0xffffffffu, lsum, off);

    __shared__ float     warpsum[8];
    __shared__ int       lastflag;
    __shared__ long long fin[2];
    if (lane == 0) warpsum[wid] = lsum;
    __syncthreads();
    if (tid == 0) {
        double s = 0.0;
        #pragma unroll
        for (int i = 0; i < 8; ++i) s += (double)warpsum[i];
        long long q = __double2ll_rn(s * FPSCALE);
        atomicAdd(&g_accs[bz], (u64)q);
        __threadfence();
        unsigned ticket = atomicInc(&g_count, NBLOCKS - 1);
        lastflag = (ticket == NBLOCKS - 1);
    }
    __syncthreads();

    if (lastflag) {
        long long v = 0;
        if (tid < NPLANES)
            v = (long long)atomicExch(&g_accs[tid], 0ULL);
        if (wid < 2) {
            #pragma unroll
            for (int off = 16; off > 0; off >>= 1)
                v += __shfl_xor_sync(0xffffffffu, v, off);
            if (lane == 0) fin[wid] = v;
        }
        __syncthreads();
        if (tid == 0) {
            long long tot = fin[0] + fin[1];
            out[0] = (float)(1.0 - ((double)tot * (1.0/FPSCALE))
                                   / (2.0 * NTOT));
        }
    }
}

extern "C" void kernel_launch(void* const* d_in, const int* in_sizes, int n_in,
                              void* d_out, int out_size)
{
    const float* F  = (const float*)d_in[0];
    const float* S1 = (const float*)d_in[1];
    const float* S2 = (const float*)d_in[2];

    static bool attr_set = false;
    if (!attr_set) {
        cudaFuncSetAttribute(ssim_fused_kernel,
                             cudaFuncAttributeMaxDynamicSharedMemorySize,
                             SMEM_BYTES);
        attr_set = true;
    }

    dim3 grid(GX, GY, NPLANES);
    ssim_fused_kernel<<<grid, NTHREADS, SMEM_BYTES>>>(F, S1, S2, (float*)d_out);
}

// round 13
// speedup vs baseline: 1.3377x; 1.3377x over previous
#include <cuda_runtime.h>
#include <cuda_fp16.h>

// ---------------------------------------------------------------------------
// SSIM fusion loss: 1 - (SSIM(f,s1)+SSIM(f,s2))/2, single fused kernel.
// 5 CTAs/SM. Halo load builds 4 half2 field-pair planes (f,a)(b,f2)(a2,b2)
// (fa,fb) once per pixel. hpass: HADD2/HFMA2 symmetric 11-tap blur on pairs.
// vpass: LDS.32 half2 + HFMA2 (unchanged from R11). Q32 reduction.
// ---------------------------------------------------------------------------

#define IMH 512
#define IMW 512
#define TW 32
#define TH 32
#define EXT 42
#define RP 44                    // cols per raw pair-plane (half2 units)
#define RROW 176                 // raw row stride in half2 = 4*RP
#define HROW2 144                // hint row stride in half2 (4 pairs * 36)
#define PST2 36                  // half2 per pair within a hint row
#define R1 24                    // phase-A hint rows (0..23)
#define RAW_H2 (EXT*RROW)        // 7392 half2 = 29568 B
#define NTHREADS 256
#define GX 16
#define GY 16
#define NPLANES 48
#define NBLOCKS (GX*GY*NPLANES)
#define NTOT 12582912.0
#define FPSCALE 4294967296.0
#define SMEM_BYTES (RAW_H2*4 + R1*HROW2*4)   // 29568 + 13824 = 43392 B

typedef unsigned long long u64;

__device__ u64      g_accs[NPLANES];
__device__ unsigned g_count = 0u;

// Gaussian weights (sigma=1.5, 11 taps, normalized) as pure literals.
#define W0f 0.00102838f
#define W1f 0.00759876f
#define W2f 0.03600077f
#define W3f 0.10936069f
#define W4f 0.21300554f
#define W5f 0.26601173f
#define WW(j) ( (j)==5 ? W5f : ((j)==4||(j)==6) ? W4f : ((j)==3||(j)==7) ? W3f \
              : ((j)==2||(j)==8) ? W2f : ((j)==1||(j)==9) ? W1f : W0f )

// half2 11-tap horizontal blur of one raw row (all 4 pair-planes), outputs
// 4 cols per plane, stored as one STS.128 per plane at HBASE (half2 units).
// Symmetric form: acc = sum_{j<5} w[j]*(v[o+j]+v[o+10-j]) + w[5]*v[o+5].
#define HPASS_H2(RAWBASE, HBASE)                                              \
{                                                                             \
    _Pragma("unroll")                                                         \
    for (int p = 0; p < 4; ++p) {                                             \
        __half2 v[16];                                                        \
        _Pragma("unroll")                                                     \
        for (int k = 0; k < 4; ++k)                                           \
            *reinterpret_cast<uint4*>(&v[4*k]) =                              \
                *reinterpret_cast<const uint4*>(&raw2[(RAWBASE) + p*RP + c0 + 4*k]); \
        __half2 acc[4];                                                       \
        _Pragma("unroll")                                                     \
        for (int o = 0; o < 4; ++o) {                                         \
            __half2 s = __hmul2(wh[0], __hadd2(v[o+0], v[o+10]));             \
            _Pragma("unroll")                                                 \
            for (int j = 1; j < 5; ++j)                                       \
                s = __hfma2(wh[j], __hadd2(v[o+j], v[o+10-j]), s);            \
            acc[o] = __hfma2(wh[5], v[o+5], s);                               \
        }                                                                     \
        *reinterpret_cast<uint4*>(&hintS[(HBASE) + p*PST2 + c0]) =            \
            *reinterpret_cast<uint4*>(acc);                                   \
    }                                                                         \
}

// vpass accumulation over 14 hint rows starting at r0v (R11 structure).
#define VPASS_LOOP(ROWPTR)                                                    \
    _Pragma("unroll")                                                         \
    for (int jj = 0; jj < 14; ++jj) {                                         \
        const int row = r0v + jj;                                             \
        const __half2* rowp = ROWPTR(row);                                    \
        __half2 v[4];                                                         \
        _Pragma("unroll")                                                     \
        for (int p = 0; p < 4; ++p)                                           \
            v[p] = rowp[p * PST2 + col];                                      \
        _Pragma("unroll")                                                     \
        for (int o = 0; o < 4; ++o) {                                         \
            const int j = jj - o;                                             \
            if (j >= 0 && j < 11) {                                           \
                const __half2 w = wh[(j < 6) ? j : (10 - j)];                 \
                _Pragma("unroll")                                             \
                for (int p = 0; p < 4; ++p)                                   \
                    acc[p][o] = __hfma2(w, v[p], acc[p][o]);                  \
            }                                                                 \
        }                                                                     \
    }

__global__ __launch_bounds__(NTHREADS, 5)
void ssim_fused_kernel(const float* __restrict__ F,
                       const float* __restrict__ S1,
                       const float* __restrict__ S2,
                       float* __restrict__ out)
{
    extern __shared__ float smemf[];
    __half2* raw2   = reinterpret_cast<__half2*>(smemf);      // [42][4][44]
    __half2* hint2A = raw2 + RAW_H2;                          // rows 0..23
    __half2* hint2B = raw2;                                   // rows 24..41 (alias)

    const int tid  = threadIdx.x;
    const int wid  = tid >> 5;
    const int lane = tid & 31;

    const int bx = blockIdx.x, by = blockIdx.y, bz = blockIdx.z;
    const int plane = bz * (IMH * IMW);
    const int y0 = by * TH - 5;

    // fp16 (w,w) weights, 6 unique — used by both passes
    __half2 wh[6];
    #pragma unroll
    for (int j = 0; j < 6; ++j) wh[j] = __floats2half2_rn(WW(j), WW(j));

    // ---- Halo load: 42 rows x 12 float4 chunks; build 4 half2 pair-planes -
    for (int i = tid; i < EXT * 12; i += NTHREADS) {
        const int q  = i % 12;
        const int r  = i / 12;
        const int gy = y0 + r;
        const int gx0 = bx * TW - 8 + q * 4;
        const bool ok = (gy >= 0) && (gy < IMH) && (gx0 >= 0) && (gx0 <= IMW - 4);

        float4 vf = make_float4(0.f,0.f,0.f,0.f);
        float4 va = vf, vb = vf;
        if (ok) {
            const int off = plane + gy * IMW + gx0;
            vf = *reinterpret_cast<const float4*>(F  + off);
            va = *reinterpret_cast<const float4*>(S1 + off);
            vb = *reinterpret_cast<const float4*>(S2 + off);
        }
        const float ff[4] = {vf.x, vf.y, vf.z, vf.w};
        const float fa[4] = {va.x, va.y, va.z, va.w};
        const float fb[4] = {vb.x, vb.y, vb.z, vb.w};

        const int cb = q * 4 - 3;
        #pragma unroll
        for (int t = 0; t < 4; ++t) {
            const int c = cb + t;
            if (c >= 0 && c < EXT) {
                const float f = ff[t], a = fa[t], b = fb[t];
                __half2 h0  = __floats2half2_rn(f, a);
                __half2 h1  = __floats2half2_rn(b, f * f);
                __half2 hab = __floats2half2_rn(a, b);
                __half2 hff = __floats2half2_rn(f, f);
                __half2 h2  = __hmul2(hab, hab);
                __half2 h3  = __hmul2(hff, hab);
                raw2[r*RROW + 0*RP + c] = h0;
                raw2[r*RROW + 1*RP + c] = h1;
                raw2[r*RROW + 2*RP + c] = h2;
                raw2[r*RROW + 3*RP + c] = h3;
            }
        }
    }
    __syncthreads();

    // ---- Horizontal pass, phase A: rows 0..23 -> hintA --------------------
    if (tid < R1 * 8) {
        const int r  = tid >> 3;
        const int c0 = (tid & 7) * 4;
        __half2* hintS = hint2A;
        HPASS_H2(r * RROW, r * HROW2)
    }
    __syncthreads();

    // ---- Phase B: rows 24..41 -> hintB at smem[0] (overlays raw rows <=17)
    if (tid < (EXT - R1) * 8) {
        const int rr = tid >> 3;            // 0..17 -> row 24+rr
        const int c0 = (tid & 7) * 4;
        __half2* hintS = hint2B;
        HPASS_H2((R1 + rr) * RROW, rr * HROW2)
    }
    __syncthreads();

    // ---- Vertical pass (half2/HFMA2) + SSIM: thread = 1 col x 4 rows ------
    const int col = lane;
    const int r0v = wid * 4;

    __half2 acc[4][4];  // [pair][out]
    #pragma unroll
    for (int p = 0; p < 4; ++p)
        #pragma unroll
        for (int o = 0; o < 4; ++o) acc[p][o] = __floats2half2_rn(0.f, 0.f);

    #define ROWPTR_A(row)   (&hint2A[(row) * HROW2])
    #define ROWPTR_MIX(row) ((row) < R1 ? &hint2A[(row) * HROW2]              \
                                        : &hint2B[((row) - R1) * HROW2])
    if (r0v + 13 < R1) {        // warps 0..2: rows entirely in hintA
        VPASS_LOOP(ROWPTR_A)
    } else {                    // warps 3..7: mixed A/B rows
        VPASS_LOOP(ROWPTR_MIX)
    }

    const float C1 = 1e-4f;
    const float C2 = 9e-4f;
    float lsum = 0.f;
    #pragma unroll
    for (int o = 0; o < 4; ++o) {
        float muF = __low2float (acc[0][o]);
        float mu1 = __high2float(acc[0][o]);
        float mu2 = __low2float (acc[1][o]);
        float eFF = __high2float(acc[1][o]);
        float e11 = __low2float (acc[2][o]);
        float e22 = __high2float(acc[2][o]);
        float eF1 = __low2float (acc[3][o]);
        float eF2 = __high2float(acc[3][o]);

        float mFF = muF*muF, m11 = mu1*mu1, m22 = mu2*mu2;
        float pF1 = muF*mu1, pF2 = muF*mu2;

        float sF  = eFF - mFF;
        float s11 = e11 - m11;
        float s22 = e22 - m22;
        float c1v = eF1 - pF1;
        float c2v = eF2 - pF2;

        float num1 = (2.f*pF1 + C1) * (2.f*c1v + C2);
        float den1 = (mFF + m11 + C1) * (sF + s11 + C2);
        float num2 = (2.f*pF2 + C1) * (2.f*c2v + C2);
        float den2 = (mFF + m22 + C1) * (sF + s22 + C2);

        lsum += __fdividef(num1*den2 + num2*den1, den1*den2);
    }

    // ---- Reduction: warp shuffle -> block -> Q32 atomic (48 slots) --------
    #pragma unroll
    for (int off = 16; off > 0; off >>= 1)
        lsum += __shfl_xor_sync(0xffffffffu, lsum, off);

    __shared__ float     warpsum[8];
    __shared__ int       lastflag;
    __shared__ long long fin[2];
    if (lane == 0) warpsum[wid] = lsum;
    __syncthreads();
    if (tid == 0) {
        double s = 0.0;
        #pragma unroll
        for (int i = 0; i < 8; ++i) s += (double)warpsum[i];
        long long q = __double2ll_rn(s * FPSCALE);
        atomicAdd(&g_accs[bz], (u64)q);
        __threadfence();
        unsigned ticket = atomicInc(&g_count, NBLOCKS - 1);
        lastflag = (ticket == NBLOCKS - 1);
    }
    __syncthreads();

    if (lastflag) {
        long long v = 0;
        if (tid < NPLANES)
            v = (long long)atomicExch(&g_accs[tid], 0ULL);
        if (wid < 2) {
            #pragma unroll
            for (int off = 16; off > 0; off >>= 1)
                v += __shfl_xor_sync(0xffffffffu, v, off);
            if (lane == 0) fin[wid] = v;
        }
        __syncthreads();
        if (tid == 0) {
            long long tot = fin[0] + fin[1];
            out[0] = (float)(1.0 - ((double)tot * (1.0/FPSCALE))
                                   / (2.0 * NTOT));
        }
    }
}

extern "C" void kernel_launch(void* const* d_in, const int* in_sizes, int n_in,
                              void* d_out, int out_size)
{
    const float* F  = (const float*)d_in[0];
    const float* S1 = (const float*)d_in[1];
    const float* S2 = (const float*)d_in[2];

    static bool attr_set = false;
    if (!attr_set) {
        cudaFuncSetAttribute(ssim_fused_kernel,
                             cudaFuncAttributeMaxDynamicSharedMemorySize,
                             SMEM_BYTES);
        attr_set = true;
    }

    dim3 grid(GX, GY, NPLANES);
    ssim_fused_kernel<<<grid, NTHREADS, SMEM_BYTES>>>(F, S1, S2, (float*)d_out);
}